// round 4
// baseline (speedup 1.0000x reference)
#include <cuda_runtime.h>
#include <math.h>

// Problem constants: T=4096, B=4, S=16 -> 64 sequences; F=64, CH=97 (16 B + 16 C + 1 A + 64 X),
// K=5, CHUNK=64, 64 chunks. N_state=16, P=64 (collapsed via red_w projection).

#define NSEQ   64
#define T_TOT  4096
#define NCHUNK 64

// ---------- device scratch (static allocations only) ----------
__device__ float g_wt[320 * 97];                 // weights transposed [f*5+k][ch]
__device__ float g_C[NSEQ * T_TOT * 16];         // C channels per (n,t)
__device__ float g_cum[NSEQ * T_TOT];            // within-chunk A cumsum
__device__ float g_base[NSEQ * T_TOT];           // y_diag + red_b + leaky(Dx)
__device__ float g_sr[NSEQ * NCHUNK * 16];       // projected chunk states
__device__ float g_dch[NSEQ * NCHUNK];           // per-chunk decay exp(clip(total))
__device__ float g_hr[NSEQ * NCHUNK * 16];       // initial projected state per chunk

__device__ __forceinline__ float clip20(float v) { return fminf(fmaxf(v, -20.f), 20.f); }

// ---------- K0: transpose conv weights [ch][f][k] -> [f*5+k][ch] ----------
__global__ void k_wt(const float* __restrict__ w) {
    int i = blockIdx.x * blockDim.x + threadIdx.x;
    if (i < 320 * 97) {
        int ch = i / 320, r = i % 320;
        g_wt[r * 97 + ch] = w[i];
    }
}

// ---------- shared memory layout (floats) ----------
// ws: 31040 | xs: 64*69 | sX: 64*65 | sB: 64*17 | sC: 64*17 | small arrays
#define WS_O    0
#define XS_O    31040
#define SX_O    35456
#define SB_O    39616
#define SC_O    40704
#define SA_O    41792
#define SCOEF_O 41856
#define SCUM_O  41920
#define SXR_O   41984
#define SWS_O   42048
#define SDEC_O  42112
#define SDX_O   42176
#define SYD_O   42240
#define SRW_O   42368
#define SPW_O   42432
#define SCB_O   42496
#define SMEMF   42600      // total floats (170400 bytes)

// ---------- K1: fused conv + activation + chunk-local scan ----------
__global__ __launch_bounds__(416, 1) void k_main(
    const float* __restrict__ x,       // (T, 4, 16, 64)
    const float* __restrict__ conv_b,  // (97,)
    const float* __restrict__ pass_w,  // (1,64)
    const float* __restrict__ pass_b,  // (1,)
    const float* __restrict__ red_w,   // (1,64)
    const float* __restrict__ red_b,   // (1,)
    const float* __restrict__ dt_param)// (1,)
{
    extern __shared__ float sm[];
    const int tid = threadIdx.x;
    const int chunk = blockIdx.x;
    const int n = blockIdx.y;
    const int b = n >> 4, s = n & 15;

    // -- cooperative loads --
    // weights (float4 copies)
    for (int i = tid; i < 31040 / 4; i += 416)
        ((float4*)(sm + WS_O))[i] = ((const float4*)g_wt)[i];
    // x tile: times [chunk*64-4, chunk*64+63], stored xs[f][lt] with stride 69 (conflict-free)
    const int t0g = chunk * 64 - 4;
    for (int i = tid; i < 68 * 64; i += 416) {
        int lt = i >> 6, f = i & 63;
        int tg = t0g + lt;
        float v = (tg >= 0) ? x[((tg * 4 + b) * 16 + s) * 64 + f] : 0.f;
        sm[XS_O + f * 69 + lt] = v;
    }
    if (tid < 64) { sm[SRW_O + tid] = red_w[tid]; sm[SPW_O + tid] = pass_w[tid]; }
    if (tid >= 64 && tid < 64 + 97) sm[SCB_O + (tid - 64)] = conv_b[tid - 64];
    const float dt = log1pf(expf(dt_param[0])) + 0.01f;
    __syncthreads();

    // -- conv: task = (ch in [0,97), h in [0,4)), 16 t per task --
    if (tid < 388) {
        const int ch = tid % 97;
        const int h = tid / 97;
        const int t0 = h * 16;
        float acc[16];
#pragma unroll
        for (int j = 0; j < 16; ++j) acc[j] = 0.f;
        const float* wp = sm + WS_O + ch;
        const float* xb = sm + XS_O + t0;
        for (int f = 0; f < 64; ++f) {
            float xv[20];
            const float* xr = xb + f * 69;
#pragma unroll
            for (int q = 0; q < 20; ++q) xv[q] = xr[q];
#pragma unroll
            for (int k = 0; k < 5; ++k) {
                float w = wp[f * 485 + k * 97];
#pragma unroll
                for (int j = 0; j < 16; ++j) acc[j] = fmaf(xv[j + k], w, acc[j]);
            }
        }
        const float bias = sm[SCB_O + ch];
#pragma unroll
        for (int j = 0; j < 16; ++j) {
            int t = t0 + j;
            float v = acc[j] + bias;
            float u = v + 1.f / (1.f + expf(-v));   // sigmoid(v)+v
            if (ch < 16)        sm[SB_O + t * 17 + ch] = u;
            else if (ch < 32)   sm[SC_O + t * 17 + (ch - 16)] = u;
            else if (ch == 32) {
                float A  = -fabsf(u);
                float la = dt * A;
                sm[SA_O + t]    = la;
                sm[SCOEF_O + t] = (expf(la) - 1.f) / (A + 1e-9f);
            } else              sm[SX_O + t * 65 + (ch - 33)] = u;
        }
    }
    __syncthreads();

    // -- phase A: warp0 scans a-> cumsum; warps1-2 compute xr and Dx --
    if (tid < 32) {
        float v0 = sm[SA_O + tid], v1 = sm[SA_O + 32 + tid];
#pragma unroll
        for (int o = 1; o < 32; o <<= 1) {
            float a0 = __shfl_up_sync(0xffffffffu, v0, o);
            float a1 = __shfl_up_sync(0xffffffffu, v1, o);
            if (tid >= o) { v0 += a0; v1 += a1; }
        }
        float tot0 = __shfl_sync(0xffffffffu, v0, 31);
        sm[SCUM_O + tid]      = v0;
        sm[SCUM_O + 32 + tid] = v1 + tot0;
    } else if (tid < 96) {
        int t = tid - 32;
        float xr = 0.f;
#pragma unroll
        for (int p = 0; p < 64; ++p) xr = fmaf(sm[SX_O + t * 65 + p], sm[SRW_O + p], xr);
        float dx = pass_b[0];
#pragma unroll
        for (int f = 0; f < 64; ++f) dx = fmaf(sm[XS_O + f * 69 + (t + 4)], sm[SPW_O + f], dx);
        sm[SXR_O + t] = xr;
        sm[SDX_O + t] = dx;
    }
    __syncthreads();

    // -- phase B: weights for diag/state terms --
    const float tot = sm[SCUM_O + 63];
    if (tid < 64) {
        sm[SWS_O + tid]  = sm[SCOEF_O + tid] * sm[SXR_O + tid];           // coef*xr
        sm[SDEC_O + tid] = expf(clip20(tot - sm[SCUM_O + tid]));          // decay_states
    }
    __syncthreads();

    // -- phase C: y_diag (128 thr), projected state (16 thr), dchunk, C export --
    if (tid < 128) {
        int l = tid & 63, hh = tid >> 6;
        float cl[16];
#pragma unroll
        for (int i = 0; i < 16; ++i) cl[i] = sm[SC_O + l * 17 + i];
        float cuml = sm[SCUM_O + l];
        float acc = 0.f;
        for (int m = hh; m <= l; m += 2) {
            float g = 0.f;
#pragma unroll
            for (int i = 0; i < 16; ++i) g = fmaf(cl[i], sm[SB_O + m * 17 + i], g);
            acc += g * sm[SWS_O + m] * expf(clip20(cuml - sm[SCUM_O + m]));
        }
        sm[SYD_O + hh * 64 + l] = acc;
    } else if (tid < 144) {
        int i = tid - 128;
        float acc = 0.f;
        for (int l = 0; l < 64; ++l)
            acc = fmaf(sm[SB_O + l * 17 + i], sm[SWS_O + l] * sm[SDEC_O + l], acc);
        g_sr[(n * 64 + chunk) * 16 + i] = acc;
    } else if (tid == 144) {
        g_dch[n * 64 + chunk] = expf(clip20(tot));
    } else if (tid >= 160) {
        for (int idx = tid - 160; idx < 1024; idx += 256) {
            int l = idx >> 4, i = idx & 15;
            g_C[((n * 64 + chunk) * 64 + l) * 16 + i] = sm[SC_O + l * 17 + i];
        }
    }
    __syncthreads();

    // -- phase D: base = y_diag + red_b + leaky(Dx); export cumsum --
    if (tid < 64) {
        int t = chunk * 64 + tid;
        float dx = sm[SDX_O + tid];
        float base = sm[SYD_O + tid] + sm[SYD_O + 64 + tid] + red_b[0]
                   + (dx >= 0.f ? dx : 0.01f * dx);
        g_base[n * 4096 + t] = base;
        g_cum[n * 4096 + t]  = sm[SCUM_O + tid];
    }
}

// ---------- K2: inter-chunk recurrence on projected 16-dim state ----------
__global__ void k_scan() {
    __shared__ float ssr[64 * 16];
    __shared__ float sdc[64];
    const int n = blockIdx.x, tid = threadIdx.x;   // 64 threads
    for (int i = tid; i < 1024; i += 64) ssr[i] = g_sr[n * 1024 + i];
    sdc[tid] = g_dch[n * 64 + tid];
    __syncthreads();
    if (tid < 16) {
        float h = 0.f;
        for (int c = 0; c < 64; ++c) {
            g_hr[(n * 64 + c) * 16 + tid] = h;
            h = sdc[c] * h + ssr[c * 16 + tid];
        }
    }
}

// ---------- K3: out = base + exp(cum) * (C . hr) ----------
__global__ void k_final(float* __restrict__ out) {
    __shared__ float hr[16];
    const int chunk = blockIdx.x, n = blockIdx.y;
    const int l = threadIdx.x;                      // 64 threads
    if (l < 16) hr[l] = g_hr[(n * 64 + chunk) * 16 + l];
    __syncthreads();
    const float* Cp = g_C + ((n * 64 + chunk) * 64 + l) * 16;
    float acc = 0.f;
#pragma unroll
    for (int i = 0; i < 16; ++i) acc = fmaf(Cp[i], hr[i], acc);
    const int t = chunk * 64 + l;
    out[t * 64 + n] = g_base[n * 4096 + t] + expf(g_cum[n * 4096 + t]) * acc;
}

// ---------- launch ----------
extern "C" void kernel_launch(void* const* d_in, const int* in_sizes, int n_in,
                              void* d_out, int out_size) {
    const float* x        = (const float*)d_in[0];
    const float* conv_w   = (const float*)d_in[1];
    const float* conv_b   = (const float*)d_in[2];
    const float* pass_w   = (const float*)d_in[3];
    const float* pass_b   = (const float*)d_in[4];
    const float* red_w    = (const float*)d_in[5];
    const float* red_b    = (const float*)d_in[6];
    const float* dt_param = (const float*)d_in[7];
    float* out = (float*)d_out;

    const int smem_bytes = SMEMF * (int)sizeof(float);
    cudaFuncSetAttribute(k_main, cudaFuncAttributeMaxDynamicSharedMemorySize, smem_bytes);

    k_wt<<<(320 * 97 + 255) / 256, 256>>>(conv_w);
    k_main<<<dim3(NCHUNK, NSEQ), 416, smem_bytes>>>(x, conv_b, pass_w, pass_b,
                                                    red_w, red_b, dt_param);
    k_scan<<<NSEQ, 64>>>();
    k_final<<<dim3(NCHUNK, NSEQ), 64>>>(out);
}

// round 5
// speedup vs baseline: 1.2474x; 1.2474x over previous
#include <cuda_runtime.h>
#include <math.h>

// T=4096, B=4, S=16 -> 64 sequences; F=64, CH=97 (16 B + 16 C + 1 A + 64 X),
// K=5, CHUNK=64, 64 chunks, N_state=16, P=64 (collapsed via red_w projection).

#define NSEQ   64
#define T_TOT  4096
#define NCHUNK 64
#define TPB    4          // chunks (tiles) per block

typedef unsigned long long u64;

__device__ __forceinline__ u64 pk2(float lo, float hi) {
    u64 r; asm("mov.b64 %0,{%1,%2};" : "=l"(r) : "f"(lo), "f"(hi)); return r;
}
__device__ __forceinline__ void upk2(u64 v, float& lo, float& hi) {
    asm("mov.b64 {%0,%1},%2;" : "=f"(lo), "=f"(hi) : "l"(v));
}
__device__ __forceinline__ u64 ffma2(u64 a, u64 b, u64 c) {
    u64 d; asm("fma.rn.f32x2 %0,%1,%2,%3;" : "=l"(d) : "l"(a), "l"(b), "l"(c)); return d;
}
__device__ __forceinline__ float clip20(float v) { return fminf(fmaxf(v, -20.f), 20.f); }

// ---------- device scratch ----------
__device__ float g_wt[320 * 97];              // conv weights transposed [f*5+k][ch]
__device__ float g_C[T_TOT * NSEQ * 16];      // [t][n][16]
__device__ float g_cum[T_TOT * NSEQ];         // [t][n]
__device__ float g_base[T_TOT * NSEQ];        // [t][n]
__device__ float g_sr[NSEQ * NCHUNK * 16];    // [n][c][16] projected chunk states
__device__ float g_dch[NSEQ * NCHUNK];        // [n][c] chunk decay
__device__ float g_hr[NCHUNK * NSEQ * 16];    // [c][n][16] initial projected state

// ---------- K0: transpose conv weights [ch][f][k] -> [f*5+k][ch] ----------
__global__ void k_wt(const float* __restrict__ w) {
    int i = blockIdx.x * blockDim.x + threadIdx.x;
    if (i < 320 * 97) {
        int ch = i / 320, r = i % 320;
        g_wt[r * 97 + ch] = w[i];
    }
}

// ---------- shared layout (floats) ----------
#define WS_O    0          // 320*97 = 31040
#define XS_O    31040      // 64*68  (x tile [f][lt], lt in [0,68), stride 68 -> 16B aligned)
#define SX_O    35392      // 64*65  (X channels [t][p])
#define SB_O    39552      // 64*17
#define SC_O    40640      // 64*17
#define SA_O    41728      // 64
#define SCOEF_O 41792      // 64
#define SCUM_O  41856      // 64
#define SWS_O   41920      // 64  (coef*xr)
#define SDEC_O  41984      // 64  (decay_states)
#define SDX_O   42048      // 64
#define SYD_O   42112      // 256 (4-way split y_diag)
#define SRW_O   42368      // 64
#define SPW_O   42432      // 64
#define SCB_O   42496      // 100
#define SMEMF   42596      // 170384 bytes

// ---------- K1: fused conv + activation + chunk-local scan, TPB chunks/block ----------
__global__ __launch_bounds__(416, 1) void k_main(
    const float* __restrict__ x,       // (T, 4, 16, 64)
    const float* __restrict__ conv_b,  // (97,)
    const float* __restrict__ pass_w,  // (1,64)
    const float* __restrict__ pass_b,  // (1,)
    const float* __restrict__ red_w,   // (1,64)
    const float* __restrict__ red_b,   // (1,)
    const float* __restrict__ dt_param)// (1,)
{
    extern __shared__ float sm[];
    const int tid = threadIdx.x;
    const int n = blockIdx.y;
    const int b = n >> 4, s = n & 15;

    // weights + small params: once per block
    for (int i = tid; i < 31040 / 4; i += 416)
        ((float4*)(sm + WS_O))[i] = ((const float4*)g_wt)[i];
    if (tid < 64) { sm[SRW_O + tid] = red_w[tid]; sm[SPW_O + tid] = pass_w[tid]; }
    if (tid >= 64 && tid < 161) sm[SCB_O + (tid - 64)] = conv_b[tid - 64];
    const float dt = log1pf(expf(dt_param[0])) + 0.01f;
    const float pb = pass_b[0], rb = red_b[0];

    for (int it = 0; it < TPB; ++it) {
        const int chunk = blockIdx.x * TPB + it;
        const int t0g = chunk * 64 - 4;
        __syncthreads();   // covers weight load (it=0) / previous tile usage

        // x tile: xs[f][lt], lt in [0,68)
        for (int i = tid; i < 68 * 64; i += 416) {
            int lt = i >> 6, f = i & 63;
            int tg = t0g + lt;
            sm[XS_O + f * 68 + lt] = (tg >= 0) ? x[((tg * 4 + b) * 16 + s) * 64 + f] : 0.f;
        }
        __syncthreads();

        // ---- conv: task = (ch, h), 16 t per task, t-pairs in fp32x2 ----
        if (tid < 388) {
            const int ch = tid % 97;
            const int h  = tid / 97;
            const int t0 = h * 16;
            u64 acc[8];
#pragma unroll
            for (int p = 0; p < 8; ++p) acc[p] = 0ULL;
            const float* wp = sm + WS_O + ch;
            const float* xb = sm + XS_O + t0;
            for (int f = 0; f < 64; ++f) {
                const float4* xq = (const float4*)(xb + f * 68);
                float4 q0 = xq[0], q1 = xq[1], q2 = xq[2], q3 = xq[3], q4 = xq[4];
                float xv[20] = {q0.x,q0.y,q0.z,q0.w, q1.x,q1.y,q1.z,q1.w,
                                q2.x,q2.y,q2.z,q2.w, q3.x,q3.y,q3.z,q3.w,
                                q4.x,q4.y,q4.z,q4.w};
                u64 xe[10], xo[9];
#pragma unroll
                for (int p = 0; p < 10; ++p) xe[p] = pk2(xv[2*p], xv[2*p+1]);
#pragma unroll
                for (int p = 0; p < 9;  ++p) xo[p] = pk2(xv[2*p+1], xv[2*p+2]);
                const float* wf = wp + f * 485;
                float w0 = wf[0], w1 = wf[97], w2 = wf[194], w3 = wf[291], w4 = wf[388];
                u64 W;
                W = pk2(w0, w0);
#pragma unroll
                for (int p = 0; p < 8; ++p) acc[p] = ffma2(xe[p], W, acc[p]);
                W = pk2(w1, w1);
#pragma unroll
                for (int p = 0; p < 8; ++p) acc[p] = ffma2(xo[p], W, acc[p]);
                W = pk2(w2, w2);
#pragma unroll
                for (int p = 0; p < 8; ++p) acc[p] = ffma2(xe[p+1], W, acc[p]);
                W = pk2(w3, w3);
#pragma unroll
                for (int p = 0; p < 8; ++p) acc[p] = ffma2(xo[p+1], W, acc[p]);
                W = pk2(w4, w4);
#pragma unroll
                for (int p = 0; p < 8; ++p) acc[p] = ffma2(xe[p+2], W, acc[p]);
            }
            const float bias = sm[SCB_O + ch];
            float u[16];
#pragma unroll
            for (int p = 0; p < 8; ++p) {
                float a0, a1; upk2(acc[p], a0, a1);
                float v0 = a0 + bias, v1 = a1 + bias;
                u[2*p]   = v0 + __fdividef(1.f, 1.f + __expf(-v0));
                u[2*p+1] = v1 + __fdividef(1.f, 1.f + __expf(-v1));
            }
            if (ch < 16) {
#pragma unroll
                for (int j = 0; j < 16; ++j) sm[SB_O + (t0 + j) * 17 + ch] = u[j];
            } else if (ch < 32) {
#pragma unroll
                for (int j = 0; j < 16; ++j) sm[SC_O + (t0 + j) * 17 + (ch - 16)] = u[j];
            } else if (ch == 32) {
#pragma unroll
                for (int j = 0; j < 16; ++j) {
                    float A  = -fabsf(u[j]);
                    float la = dt * A;
                    sm[SA_O + t0 + j]    = la;
                    sm[SCOEF_O + t0 + j] = (__expf(la) - 1.f) / (A + 1e-9f);
                }
            } else {
#pragma unroll
                for (int j = 0; j < 16; ++j) sm[SX_O + (t0 + j) * 65 + (ch - 33)] = u[j];
            }
        }
        __syncthreads();

        // ---- phase A: scan + decay (warp0), coef*xr + Dx (warps1-2), C export (96..223) ----
        if (tid < 32) {
            float v0 = sm[SA_O + tid], v1 = sm[SA_O + 32 + tid];
#pragma unroll
            for (int o = 1; o < 32; o <<= 1) {
                float a0 = __shfl_up_sync(0xffffffffu, v0, o);
                float a1 = __shfl_up_sync(0xffffffffu, v1, o);
                if (tid >= o) { v0 += a0; v1 += a1; }
            }
            float tot0  = __shfl_sync(0xffffffffu, v0, 31);
            float cum_b = v1 + tot0;
            float tot   = __shfl_sync(0xffffffffu, cum_b, 31);
            sm[SCUM_O + tid]      = v0;
            sm[SCUM_O + 32 + tid] = cum_b;
            sm[SDEC_O + tid]      = __expf(clip20(tot - v0));
            sm[SDEC_O + 32 + tid] = __expf(clip20(tot - cum_b));
            if (tid == 31) g_dch[n * 64 + chunk] = __expf(clip20(tot));
        } else if (tid < 96) {
            int t = tid - 32;
            float xr = 0.f;
#pragma unroll
            for (int p = 0; p < 64; ++p) xr = fmaf(sm[SX_O + t * 65 + p], sm[SRW_O + p], xr);
            float dx = pb;
#pragma unroll
            for (int f = 0; f < 64; ++f) dx = fmaf(sm[XS_O + f * 68 + (t + 4)], sm[SPW_O + f], dx);
            sm[SWS_O + t] = xr * sm[SCOEF_O + t];
            sm[SDX_O + t] = dx;
        } else if (tid < 224) {
            for (int idx = tid - 96; idx < 1024; idx += 128) {
                int l = idx >> 4, i = idx & 15;
                g_C[(((chunk * 64 + l) * 64) + n) * 16 + i] = sm[SC_O + l * 17 + i];
            }
        }
        __syncthreads();

        // ---- phase C: y_diag 4-way (256 thr) + projected state (16 thr) ----
        if (tid < 256) {
            int l = tid & 63, hh = tid >> 6;
            float cl[16];
#pragma unroll
            for (int i = 0; i < 16; ++i) cl[i] = sm[SC_O + l * 17 + i];
            float cuml = sm[SCUM_O + l];
            float acc = 0.f;
            for (int m = hh; m <= l; m += 4) {
                float g = 0.f;
#pragma unroll
                for (int i = 0; i < 16; ++i) g = fmaf(cl[i], sm[SB_O + m * 17 + i], g);
                acc += g * sm[SWS_O + m] * __expf(clip20(cuml - sm[SCUM_O + m]));
            }
            sm[SYD_O + hh * 64 + l] = acc;
        } else if (tid < 272) {
            int i = tid - 256;
            float acc = 0.f;
            for (int l = 0; l < 64; ++l)
                acc = fmaf(sm[SB_O + l * 17 + i], sm[SWS_O + l] * sm[SDEC_O + l], acc);
            g_sr[(n * 64 + chunk) * 16 + i] = acc;
        }
        __syncthreads();

        // ---- phase D: base + cum export, [t][n] layouts ----
        if (tid < 64) {
            int t = chunk * 64 + tid;
            float dx   = sm[SDX_O + tid];
            float base = sm[SYD_O + tid] + sm[SYD_O + 64 + tid]
                       + sm[SYD_O + 128 + tid] + sm[SYD_O + 192 + tid] + rb
                       + (dx >= 0.f ? dx : 0.01f * dx);
            g_base[t * 64 + n] = base;
            g_cum[t * 64 + n]  = sm[SCUM_O + tid];
        }
    }
}

// ---------- K2: inter-chunk recurrence on projected 16-dim state ----------
__global__ void k_scan() {
    __shared__ float ssr[64 * 16];
    __shared__ float sdc[64];
    const int n = blockIdx.x, tid = threadIdx.x;   // 64 threads
    for (int i = tid; i < 1024; i += 64) ssr[i] = g_sr[n * 1024 + i];
    sdc[tid] = g_dch[n * 64 + tid];
    __syncthreads();
    if (tid < 16) {
        float h = 0.f;
        for (int c = 0; c < 64; ++c) {
            g_hr[(c * 64 + n) * 16 + tid] = h;
            h = sdc[c] * h + ssr[c * 16 + tid];
        }
    }
}

// ---------- K3: out = base + exp(cum) * (C . hr), coalesced over n ----------
__global__ __launch_bounds__(512) void k_final(float* __restrict__ out) {
    __shared__ float hr[1024];
    const int chunk = blockIdx.x;
    const int tid = threadIdx.x;
    for (int i = tid; i < 1024; i += 512) hr[i] = g_hr[chunk * 1024 + i];
    __syncthreads();
    const int nn = tid & 63;
    for (int l = tid >> 6; l < 64; l += 8) {
        const int t = chunk * 64 + l;
        const float4* Cp = (const float4*)(g_C + (t * 64 + nn) * 16);
        float4 c0 = Cp[0], c1 = Cp[1], c2 = Cp[2], c3 = Cp[3];
        const float* h = hr + nn * 16;
        float acc = c0.x*h[0] + c0.y*h[1] + c0.z*h[2] + c0.w*h[3]
                  + c1.x*h[4] + c1.y*h[5] + c1.z*h[6] + c1.w*h[7]
                  + c2.x*h[8] + c2.y*h[9] + c2.z*h[10] + c2.w*h[11]
                  + c3.x*h[12] + c3.y*h[13] + c3.z*h[14] + c3.w*h[15];
        out[t * 64 + nn] = g_base[t * 64 + nn] + __expf(g_cum[t * 64 + nn]) * acc;
    }
}

// ---------- launch ----------
extern "C" void kernel_launch(void* const* d_in, const int* in_sizes, int n_in,
                              void* d_out, int out_size) {
    const float* x        = (const float*)d_in[0];
    const float* conv_w   = (const float*)d_in[1];
    const float* conv_b   = (const float*)d_in[2];
    const float* pass_w   = (const float*)d_in[3];
    const float* pass_b   = (const float*)d_in[4];
    const float* red_w    = (const float*)d_in[5];
    const float* red_b    = (const float*)d_in[6];
    const float* dt_param = (const float*)d_in[7];
    float* out = (float*)d_out;

    const int smem_bytes = SMEMF * (int)sizeof(float);
    cudaFuncSetAttribute(k_main, cudaFuncAttributeMaxDynamicSharedMemorySize, smem_bytes);

    k_wt<<<(320 * 97 + 255) / 256, 256>>>(conv_w);
    k_main<<<dim3(NCHUNK / TPB, NSEQ), 416, smem_bytes>>>(x, conv_b, pass_w, pass_b,
                                                          red_w, red_b, dt_param);
    k_scan<<<NSEQ, 64>>>();
    k_final<<<NCHUNK, 512>>>(out);
}

// round 6
// speedup vs baseline: 2.6109x; 2.0930x over previous
#include <cuda_runtime.h>
#include <math.h>

// T=4096, B=4, S=16 -> 64 sequences; F=64, CH=97 (16 B + 16 C + 1 A + 64 X),
// K=5, CHUNK=64, 64 chunks, N_state=16, P=64 (collapsed via red_w projection).
// Conv done as tf32 mma.sync GEMM: per chunk [64 t] x [320 fk] x [104 chp].

#define NSEQ   64
#define T_TOT  4096
#define NCHUNK 64
#define TPB    4

__device__ __forceinline__ unsigned tf32r(float x) {
    unsigned u; asm("cvt.rna.tf32.f32 %0,%1;" : "=r"(u) : "f"(x)); return u;
}
__device__ __forceinline__ float clip20(float v) { return fminf(fmaxf(v, -20.f), 20.f); }

// ---------- device scratch ----------
__device__ float g_wB[320 * 104];             // B matrix [kk=k*64+f][chp], tf32, zero-pad ch>=97
__device__ float g_C[T_TOT * NSEQ * 16];      // [t][n][16]
__device__ float g_cum[T_TOT * NSEQ];         // [t][n]
__device__ float g_base[T_TOT * NSEQ];        // [t][n]
__device__ float g_sr[NSEQ * NCHUNK * 16];    // [n][c][16]
__device__ float g_dch[NSEQ * NCHUNK];        // [n][c]
__device__ float g_hr[NCHUNK * NSEQ * 16];    // [c][n][16]

// ---------- K0: build B matrix: g_wB[kk][chp] = tf32(conv_w[ch][f][k]) ----------
__global__ void k_wt(const float* __restrict__ w) {
    int i = blockIdx.x * blockDim.x + threadIdx.x;
    if (i < 320 * 104) {
        int kk = i / 104, chp = i % 104;
        int k = kk >> 6, f = kk & 63;
        float v = (chp < 97) ? w[chp * 320 + f * 5 + k] : 0.f;
        g_wB[i] = __uint_as_float(tf32r(v));
    }
}

// ---------- shared layout (floats) ----------
#define WB_O    0          // 320*104 = 33280
#define XS_O    33280      // 64*72 (x tile [f][lt], stride 72 -> conflict-free A frags)
#define SX_O    37888      // 64*65
#define SB_O    42048      // 64*17
#define SC_O    43136      // 64*17
#define SA_O    44224      // 64
#define SCOEF_O 44288      // 64
#define SCUM_O  44352      // 64
#define SWS_O   44416      // 64
#define SDEC_O  44480      // 64
#define SDX_O   44544      // 64
#define SYD_O   44608      // 192 (3-way split)
#define SRW_O   44800      // 64
#define SPW_O   44864      // 64
#define SCB_O   44928      // 104 (zero-padded)
#define SMEMF   45032      // 180128 bytes

// ---------- K1: fused tf32-MMA conv + activation + chunk-local scan ----------
__global__ __launch_bounds__(256, 1) void k_main(
    const float* __restrict__ x,       // (T, 4, 16, 64)
    const float* __restrict__ conv_b,  // (97,)
    const float* __restrict__ pass_w,  // (1,64)
    const float* __restrict__ pass_b,  // (1,)
    const float* __restrict__ red_w,   // (1,64)
    const float* __restrict__ red_b,   // (1,)
    const float* __restrict__ dt_param)// (1,)
{
    extern __shared__ float sm[];
    const int tid = threadIdx.x;
    const int lane = tid & 31;
    const int wid = tid >> 5;           // 8 warps
    const int n = blockIdx.y;
    const int b = n >> 4, s = n & 15;

    // block-wide constants + B tile (once per block)
    for (int i = tid; i < 33280 / 4; i += 256)
        ((float4*)(sm + WB_O))[i] = ((const float4*)g_wB)[i];
    if (tid < 64) { sm[SRW_O + tid] = red_w[tid]; sm[SPW_O + tid] = pass_w[tid]; }
    if (tid >= 64 && tid < 168) sm[SCB_O + (tid - 64)] = (tid - 64 < 97) ? conv_b[tid - 64] : 0.f;
    const float dt = log1pf(expf(dt_param[0])) + 0.01f;
    const float pb = pass_b[0], rb = red_b[0];

    // warp roles for mma: mpair (t rows 0-31 / 32-63), nset (ntile groups {0-3},{4-6},{7-9},{10-12})
    const int mpair = wid >> 2;
    const int nset  = wid & 3;
    const int nt    = nset ? 3 : 4;
    const int nb8   = (nset ? (4 + 3 * (nset - 1)) : 0) * 8;
    const int lc = lane & 3, lr = lane >> 2;

    for (int it = 0; it < TPB; ++it) {
        const int chunk = blockIdx.x * TPB + it;
        const int t0g = chunk * 64 - 4;
        __syncthreads();

        // x tile -> smem (tf32-rounded), xs[f][lt], stride 72
        for (int i = tid; i < 68 * 64; i += 256) {
            int lt = i >> 6, f = i & 63;
            int tg = t0g + lt;
            float v = (tg >= 0) ? x[((tg * 4 + b) * 16 + s) * 64 + f] : 0.f;
            sm[XS_O + f * 72 + lt] = __uint_as_float(tf32r(v));
        }
        __syncthreads();

        // ---- tf32 MMA: out[t][ch] = sum_kk A[t][kk] * B[kk][ch] ----
        float acc[2][4][4];
#pragma unroll
        for (int mt = 0; mt < 2; ++mt)
#pragma unroll
            for (int q = 0; q < 4; ++q)
#pragma unroll
                for (int e = 0; e < 4; ++e) acc[mt][q][e] = 0.f;

        const unsigned* xs_u = (const unsigned*)(sm + XS_O);
        const unsigned* wb_u = (const unsigned*)(sm + WB_O);

        for (int ks = 0; ks < 40; ++ks) {
            const int kk0 = ks * 8;
            // A[t][kk] = xs[f=kk&63][t + (kk>>6)]
            const unsigned* ap = xs_u + ((kk0 & 63) + lc) * 72 + (kk0 >> 6) + lr + mpair * 32;
            const unsigned* bp = wb_u + (kk0 + lc) * 104 + nb8 + lr;
            unsigned a[2][4];
#pragma unroll
            for (int mt = 0; mt < 2; ++mt) {
                a[mt][0] = ap[mt * 16];
                a[mt][1] = ap[mt * 16 + 8];
                a[mt][2] = ap[mt * 16 + 288];     // f+4
                a[mt][3] = ap[mt * 16 + 296];
            }
#pragma unroll
            for (int q = 0; q < 4; ++q) {
                if (q < nt) {
                    unsigned b0 = bp[q * 8];
                    unsigned b1 = bp[q * 8 + 416]; // kk+4
#pragma unroll
                    for (int mt = 0; mt < 2; ++mt) {
                        asm volatile(
                            "mma.sync.aligned.m16n8k8.row.col.f32.tf32.tf32.f32 "
                            "{%0,%1,%2,%3},{%4,%5,%6,%7},{%8,%9},{%0,%1,%2,%3};"
                            : "+f"(acc[mt][q][0]), "+f"(acc[mt][q][1]),
                              "+f"(acc[mt][q][2]), "+f"(acc[mt][q][3])
                            : "r"(a[mt][0]), "r"(a[mt][1]), "r"(a[mt][2]), "r"(a[mt][3]),
                              "r"(b0), "r"(b1));
                    }
                }
            }
        }

        // ---- epilogue: bias + gate (u = v + sigmoid(v)) + scatter ----
#pragma unroll
        for (int mt = 0; mt < 2; ++mt) {
#pragma unroll
            for (int q = 0; q < 4; ++q) {
                if (q < nt) {
                    const int ch0 = nb8 + q * 8 + 2 * lc;
                    const int t0r = mpair * 32 + mt * 16 + lr;
#pragma unroll
                    for (int e = 0; e < 4; ++e) {
                        const int ch = ch0 + (e & 1);
                        const int t  = t0r + (e >> 1) * 8;
                        float v = acc[mt][q][e] + sm[SCB_O + ch];
                        float u = v + __fdividef(1.f, 1.f + __expf(-v));
                        if (ch < 16)       sm[SB_O + t * 17 + ch] = u;
                        else if (ch < 32)  sm[SC_O + t * 17 + (ch - 16)] = u;
                        else if (ch == 32) {
                            float A  = -fabsf(u);
                            float la = dt * A;
                            sm[SA_O + t]    = la;
                            sm[SCOEF_O + t] = (__expf(la) - 1.f) / (A + 1e-9f);
                        } else if (ch < 97) sm[SX_O + t * 65 + (ch - 33)] = u;
                    }
                }
            }
        }
        __syncthreads();

        // ---- phase A: scan (warp0), xr/Dx (32..95), C export (96..223) ----
        if (tid < 32) {
            float v0 = sm[SA_O + tid], v1 = sm[SA_O + 32 + tid];
#pragma unroll
            for (int o = 1; o < 32; o <<= 1) {
                float a0 = __shfl_up_sync(0xffffffffu, v0, o);
                float a1 = __shfl_up_sync(0xffffffffu, v1, o);
                if (tid >= o) { v0 += a0; v1 += a1; }
            }
            float tot0  = __shfl_sync(0xffffffffu, v0, 31);
            float cum_b = v1 + tot0;
            float tot   = __shfl_sync(0xffffffffu, cum_b, 31);
            sm[SCUM_O + tid]      = v0;
            sm[SCUM_O + 32 + tid] = cum_b;
            sm[SDEC_O + tid]      = __expf(clip20(tot - v0));
            sm[SDEC_O + 32 + tid] = __expf(clip20(tot - cum_b));
            if (tid == 31) g_dch[n * 64 + chunk] = __expf(clip20(tot));
        } else if (tid < 96) {
            int t = tid - 32;
            float xr = 0.f;
#pragma unroll
            for (int p = 0; p < 64; ++p) xr = fmaf(sm[SX_O + t * 65 + p], sm[SRW_O + p], xr);
            float dx = pb;
#pragma unroll
            for (int f = 0; f < 64; ++f) dx = fmaf(sm[XS_O + f * 72 + (t + 4)], sm[SPW_O + f], dx);
            sm[SWS_O + t] = xr * sm[SCOEF_O + t];
            sm[SDX_O + t] = dx;
        } else if (tid < 224) {
            for (int idx = tid - 96; idx < 1024; idx += 128) {
                int l = idx >> 4, i = idx & 15;
                g_C[(((chunk * 64 + l) * 64) + n) * 16 + i] = sm[SC_O + l * 17 + i];
            }
        }
        __syncthreads();

        // ---- phase C: y_diag 3-way (0..191) + projected state (192..207) ----
        if (tid < 192) {
            int l = tid & 63, hh = tid >> 6;
            float cl[16];
#pragma unroll
            for (int i = 0; i < 16; ++i) cl[i] = sm[SC_O + l * 17 + i];
            float cuml = sm[SCUM_O + l];
            float acc2 = 0.f;
            for (int m = hh; m <= l; m += 3) {
                float g = 0.f;
#pragma unroll
                for (int i = 0; i < 16; ++i) g = fmaf(cl[i], sm[SB_O + m * 17 + i], g);
                acc2 += g * sm[SWS_O + m] * __expf(clip20(cuml - sm[SCUM_O + m]));
            }
            sm[SYD_O + hh * 64 + l] = acc2;
        } else if (tid < 208) {
            int i = tid - 192;
            float acc2 = 0.f;
            for (int l = 0; l < 64; ++l)
                acc2 = fmaf(sm[SB_O + l * 17 + i], sm[SWS_O + l] * sm[SDEC_O + l], acc2);
            g_sr[(n * 64 + chunk) * 16 + i] = acc2;
        }
        __syncthreads();

        // ---- phase D ----
        if (tid < 64) {
            int t = chunk * 64 + tid;
            float dx   = sm[SDX_O + tid];
            float base = sm[SYD_O + tid] + sm[SYD_O + 64 + tid] + sm[SYD_O + 128 + tid] + rb
                       + (dx >= 0.f ? dx : 0.01f * dx);
            g_base[t * 64 + n] = base;
            g_cum[t * 64 + n]  = sm[SCUM_O + tid];
        }
    }
}

// ---------- K2: inter-chunk recurrence on projected 16-dim state ----------
__global__ void k_scan() {
    __shared__ float ssr[64 * 16];
    __shared__ float sdc[64];
    const int n = blockIdx.x, tid = threadIdx.x;   // 64 threads
    for (int i = tid; i < 1024; i += 64) ssr[i] = g_sr[n * 1024 + i];
    sdc[tid] = g_dch[n * 64 + tid];
    __syncthreads();
    if (tid < 16) {
        float h = 0.f;
        for (int c = 0; c < 64; ++c) {
            g_hr[(c * 64 + n) * 16 + tid] = h;
            h = sdc[c] * h + ssr[c * 16 + tid];
        }
    }
}

// ---------- K3: out = base + exp(cum) * (C . hr) ----------
__global__ __launch_bounds__(256) void k_final(float* __restrict__ out) {
    __shared__ float hr[1024];
    const int chunk = blockIdx.x;
    const int quad  = blockIdx.y;
    const int tid = threadIdx.x;
    for (int i = tid; i < 1024; i += 256) hr[i] = g_hr[chunk * 1024 + i];
    __syncthreads();
    const int nn = tid & 63;
    const int l0 = quad * 16 + (tid >> 6);
    for (int l = l0; l < quad * 16 + 16; l += 4) {
        const int t = chunk * 64 + l;
        const float4* Cp = (const float4*)(g_C + (t * 64 + nn) * 16);
        float4 c0 = Cp[0], c1 = Cp[1], c2 = Cp[2], c3 = Cp[3];
        const float* h = hr + nn * 16;
        float acc = c0.x*h[0] + c0.y*h[1] + c0.z*h[2] + c0.w*h[3]
                  + c1.x*h[4] + c1.y*h[5] + c1.z*h[6] + c1.w*h[7]
                  + c2.x*h[8] + c2.y*h[9] + c2.z*h[10] + c2.w*h[11]
                  + c3.x*h[12] + c3.y*h[13] + c3.z*h[14] + c3.w*h[15];
        out[t * 64 + nn] = g_base[t * 64 + nn] + __expf(g_cum[t * 64 + nn]) * acc;
    }
}

// ---------- launch ----------
extern "C" void kernel_launch(void* const* d_in, const int* in_sizes, int n_in,
                              void* d_out, int out_size) {
    const float* x        = (const float*)d_in[0];
    const float* conv_w   = (const float*)d_in[1];
    const float* conv_b   = (const float*)d_in[2];
    const float* pass_w   = (const float*)d_in[3];
    const float* pass_b   = (const float*)d_in[4];
    const float* red_w    = (const float*)d_in[5];
    const float* red_b    = (const float*)d_in[6];
    const float* dt_param = (const float*)d_in[7];
    float* out = (float*)d_out;

    const int smem_bytes = SMEMF * (int)sizeof(float);
    cudaFuncSetAttribute(k_main, cudaFuncAttributeMaxDynamicSharedMemorySize, smem_bytes);

    k_wt<<<(320 * 104 + 255) / 256, 256>>>(conv_w);
    k_main<<<dim3(NCHUNK / TPB, NSEQ), 256, smem_bytes>>>(x, conv_b, pass_w, pass_b,
                                                          red_w, red_b, dt_param);
    k_scan<<<NSEQ, 64>>>();
    k_final<<<dim3(NCHUNK, 4), 256>>>(out);
}

// round 7
// speedup vs baseline: 2.8272x; 1.0828x over previous
#include <cuda_runtime.h>
#include <math.h>

// T=4096, B=4, S=16 -> 64 sequences; F=64, CH=97 (16 B + 16 C + 1 A + 64 X),
// K=5, CHUNK=64, 64 chunks, N_state=16, P=64 (collapsed via red_w projection).
// Conv as tf32 mma GEMM [64 t][320 fk][104 chp]; Gram G=C*B^T also on tensor cores.

#define NSEQ   64
#define T_TOT  4096
#define NCHUNK 64
#define TPB    4

__device__ __forceinline__ unsigned tf32r(float x) {
    unsigned u; asm("cvt.rna.tf32.f32 %0,%1;" : "=r"(u) : "f"(x)); return u;
}
__device__ __forceinline__ float clip20(float v) { return fminf(fmaxf(v, -20.f), 20.f); }
__device__ __forceinline__ void cpa4(unsigned dst, const float* src, int sz) {
    asm volatile("cp.async.ca.shared.global [%0],[%1],4,%2;" :: "r"(dst), "l"(src), "r"(sz));
}

// ---------- device scratch ----------
__device__ float g_wB[320 * 104];             // [kk][chp], tf32, zero-pad ch>=97
__device__ float g_C[T_TOT * NSEQ * 16];      // [t][n][16]
__device__ float g_cum[T_TOT * NSEQ];         // [t][n]
__device__ float g_base[T_TOT * NSEQ];        // [t][n]
__device__ float g_sr[NSEQ * NCHUNK * 16];
__device__ float g_dch[NSEQ * NCHUNK];
__device__ float g_hr[NCHUNK * NSEQ * 16];    // [c][n][16]

// ---------- K0: build B matrix ----------
__global__ void k_wt(const float* __restrict__ w) {
    int i = blockIdx.x * blockDim.x + threadIdx.x;
    if (i < 320 * 104) {
        int kk = i / 104, chp = i % 104;
        int k = kk >> 6, f = kk & 63;
        float v = (chp < 97) ? w[chp * 320 + f * 5 + k] : 0.f;
        g_wB[i] = __uint_as_float(tf32r(v));
    }
}

// ---------- shared layout (floats) ----------
#define WB_O    0          // 33280
#define XS0_O   33280      // 64*72
#define XS1_O   37888      // 64*72
#define SX_O    42496      // 64*65
#define SB_O    46656      // 64*17
#define SC_O    47744      // 64*17
#define SG_O    48832      // 64*65 Gram
#define SA_O    52992
#define SCOEF_O 53056
#define SCUM_O  53120
#define SWS_O   53184
#define SDEC_O  53248
#define SDX_O   53312
#define SYD_O   53376      // 192
#define SSR_O   53568      // 64
#define SRW_O   53632
#define SPW_O   53696
#define SCB_O   53760      // 104
#define SMEMF   53864      // 215456 bytes

// ---------- K1 ----------
__global__ __launch_bounds__(256, 1) void k_main(
    const float* __restrict__ x,
    const float* __restrict__ conv_b,
    const float* __restrict__ pass_w,
    const float* __restrict__ pass_b,
    const float* __restrict__ red_w,
    const float* __restrict__ red_b,
    const float* __restrict__ dt_param)
{
    extern __shared__ float sm[];
    const int tid  = threadIdx.x;
    const int lane = tid & 31;
    const int wid  = tid >> 5;
    const int n = blockIdx.y;
    const int b = n >> 4, s = n & 15;

    for (int i = tid; i < 33280 / 4; i += 256)
        ((float4*)(sm + WB_O))[i] = ((const float4*)g_wB)[i];
    if (tid < 64) { sm[SRW_O + tid] = red_w[tid]; sm[SPW_O + tid] = pass_w[tid]; }
    if (tid >= 64 && tid < 168) sm[SCB_O + (tid - 64)] = (tid - 64 < 97) ? conv_b[tid - 64] : 0.f;
    const float dt = log1pf(expf(dt_param[0])) + 0.01f;
    const float pb = pass_b[0], rb = red_b[0];

    const int mpair = wid >> 2;
    const int nset  = wid & 3;
    const int nt    = nset ? 3 : 4;
    const int nb8   = (nset ? (4 + 3 * (nset - 1)) : 0) * 8;
    const int lc = lane & 3, lr = lane >> 2;

    const int chunk0 = blockIdx.x * TPB;

    // prologue: cp.async x tile of chunk0 into XS0
    {
        const int t0g = chunk0 * 64 - 4;
        for (int i = tid; i < 68 * 64; i += 256) {
            int lt = i >> 6, f = i & 63;
            int tg = t0g + lt;
            unsigned dst = (unsigned)__cvta_generic_to_shared(sm + XS0_O + f * 72 + lt);
            cpa4(dst, x + ((tg * 4 + b) * 16 + s) * 64 + f, (tg >= 0) ? 4 : 0);
        }
        asm volatile("cp.async.commit_group;" ::: "memory");
    }

    for (int it = 0; it < TPB; ++it) {
        const int chunk = chunk0 + it;
        const int cur_o = (it & 1) ? XS1_O : XS0_O;
        asm volatile("cp.async.wait_group 0;" ::: "memory");
        __syncthreads();

        // issue prefetch for next chunk into other buffer
        if (it + 1 < TPB) {
            const int t0g = (chunk + 1) * 64 - 4;
            const int nxt_o = (it & 1) ? XS0_O : XS1_O;
            for (int i = tid; i < 68 * 64; i += 256) {
                int lt = i >> 6, f = i & 63;
                int tg = t0g + lt;
                unsigned dst = (unsigned)__cvta_generic_to_shared(sm + nxt_o + f * 72 + lt);
                cpa4(dst, x + ((tg * 4 + b) * 16 + s) * 64 + f, 4);
            }
            asm volatile("cp.async.commit_group;" ::: "memory");
        }

        // in-place tf32 rounding of current tile
        for (int i = tid; i < 68 * 64; i += 256) {
            int lt = i >> 6, f = i & 63;
            float* p = sm + cur_o + f * 72 + lt;
            *p = __uint_as_float(tf32r(*p));
        }
        __syncthreads();

        // ---- conv MMA ----
        float acc[2][4][4];
#pragma unroll
        for (int mt = 0; mt < 2; ++mt)
#pragma unroll
            for (int q = 0; q < 4; ++q)
#pragma unroll
                for (int e = 0; e < 4; ++e) acc[mt][q][e] = 0.f;

        const unsigned* xs_u = (const unsigned*)(sm + cur_o);
        const unsigned* wb_u = (const unsigned*)(sm + WB_O);

        for (int ks = 0; ks < 40; ++ks) {
            const int kk0 = ks * 8;
            const unsigned* ap = xs_u + ((kk0 & 63) + lc) * 72 + (kk0 >> 6) + lr + mpair * 32;
            const unsigned* bp = wb_u + (kk0 + lc) * 104 + nb8 + lr;
            unsigned a[2][4];
#pragma unroll
            for (int mt = 0; mt < 2; ++mt) {
                a[mt][0] = ap[mt * 16];
                a[mt][1] = ap[mt * 16 + 8];
                a[mt][2] = ap[mt * 16 + 288];
                a[mt][3] = ap[mt * 16 + 296];
            }
#pragma unroll
            for (int q = 0; q < 4; ++q) {
                if (q < nt) {
                    unsigned b0 = bp[q * 8];
                    unsigned b1 = bp[q * 8 + 416];
#pragma unroll
                    for (int mt = 0; mt < 2; ++mt) {
                        asm volatile(
                            "mma.sync.aligned.m16n8k8.row.col.f32.tf32.tf32.f32 "
                            "{%0,%1,%2,%3},{%4,%5,%6,%7},{%8,%9},{%0,%1,%2,%3};"
                            : "+f"(acc[mt][q][0]), "+f"(acc[mt][q][1]),
                              "+f"(acc[mt][q][2]), "+f"(acc[mt][q][3])
                            : "r"(a[mt][0]), "r"(a[mt][1]), "r"(a[mt][2]), "r"(a[mt][3]),
                              "r"(b0), "r"(b1));
                    }
                }
            }
        }

        // ---- epilogue: bias + (v + sigmoid(v)) + scatter ----
#pragma unroll
        for (int mt = 0; mt < 2; ++mt) {
#pragma unroll
            for (int q = 0; q < 4; ++q) {
                if (q < nt) {
                    const int ch0 = nb8 + q * 8 + 2 * lc;
                    const int t0r = mpair * 32 + mt * 16 + lr;
#pragma unroll
                    for (int e = 0; e < 4; ++e) {
                        const int ch = ch0 + (e & 1);
                        const int t  = t0r + (e >> 1) * 8;
                        float v = acc[mt][q][e] + sm[SCB_O + ch];
                        float u = v + __fdividef(1.f, 1.f + __expf(-v));
                        if (ch < 16)       sm[SB_O + t * 17 + ch] = u;
                        else if (ch < 32)  sm[SC_O + t * 17 + (ch - 16)] = u;
                        else if (ch == 32) {
                            float A  = -fabsf(u);
                            float la = dt * A;
                            sm[SA_O + t]    = la;
                            sm[SCOEF_O + t] = (__expf(la) - 1.f) / (A + 1e-9f);
                        } else if (ch < 97) sm[SX_O + t * 65 + (ch - 33)] = u;
                    }
                }
            }
        }
        __syncthreads();

        // ---- concurrent phase: scan | xr/Dx | C export | Gram MMA ----
        if (tid < 32) {
            float v0 = sm[SA_O + tid], v1 = sm[SA_O + 32 + tid];
#pragma unroll
            for (int o = 1; o < 32; o <<= 1) {
                float a0 = __shfl_up_sync(0xffffffffu, v0, o);
                float a1 = __shfl_up_sync(0xffffffffu, v1, o);
                if (tid >= o) { v0 += a0; v1 += a1; }
            }
            float tot0  = __shfl_sync(0xffffffffu, v0, 31);
            float cum_b = v1 + tot0;
            float tot   = __shfl_sync(0xffffffffu, cum_b, 31);
            sm[SCUM_O + tid]      = v0;
            sm[SCUM_O + 32 + tid] = cum_b;
            sm[SDEC_O + tid]      = __expf(clip20(tot - v0));
            sm[SDEC_O + 32 + tid] = __expf(clip20(tot - cum_b));
            if (tid == 31) g_dch[n * 64 + chunk] = __expf(clip20(tot));
        } else if (tid < 96) {
            int t = tid - 32;
            float xr = 0.f;
#pragma unroll
            for (int p = 0; p < 64; ++p) xr = fmaf(sm[SX_O + t * 65 + p], sm[SRW_O + p], xr);
            float dx = pb;
#pragma unroll
            for (int f = 0; f < 64; ++f) dx = fmaf(sm[cur_o + f * 72 + (t + 4)], sm[SPW_O + f], dx);
            sm[SWS_O + t] = xr * sm[SCOEF_O + t];
            sm[SDX_O + t] = dx;
        } else if (tid < 128) {
            for (int idx = tid - 96; idx < 1024; idx += 32) {
                int l = idx >> 4, i = idx & 15;
                g_C[(((chunk * 64 + l) * 64) + n) * 16 + i] = sm[SC_O + l * 17 + i];
            }
        } else {
            // Gram: G[l][m] = sum_i C[l][i]*B[m][i]; warp w handles mtile = w
            const int w = wid - 4;
            float g[8][4];
#pragma unroll
            for (int q = 0; q < 8; ++q)
#pragma unroll
                for (int e = 0; e < 4; ++e) g[q][e] = 0.f;
#pragma unroll
            for (int k0 = 0; k0 < 16; k0 += 8) {
                unsigned a0 = tf32r(sm[SC_O + (w * 16 + lr) * 17 + k0 + lc]);
                unsigned a1 = tf32r(sm[SC_O + (w * 16 + 8 + lr) * 17 + k0 + lc]);
                unsigned a2 = tf32r(sm[SC_O + (w * 16 + lr) * 17 + k0 + lc + 4]);
                unsigned a3 = tf32r(sm[SC_O + (w * 16 + 8 + lr) * 17 + k0 + lc + 4]);
#pragma unroll
                for (int q = 0; q < 8; ++q) {
                    unsigned b0 = tf32r(sm[SB_O + (q * 8 + lr) * 17 + k0 + lc]);
                    unsigned b1 = tf32r(sm[SB_O + (q * 8 + lr) * 17 + k0 + lc + 4]);
                    asm volatile(
                        "mma.sync.aligned.m16n8k8.row.col.f32.tf32.tf32.f32 "
                        "{%0,%1,%2,%3},{%4,%5,%6,%7},{%8,%9},{%0,%1,%2,%3};"
                        : "+f"(g[q][0]), "+f"(g[q][1]), "+f"(g[q][2]), "+f"(g[q][3])
                        : "r"(a0), "r"(a1), "r"(a2), "r"(a3), "r"(b0), "r"(b1));
                }
            }
#pragma unroll
            for (int q = 0; q < 8; ++q) {
                sm[SG_O + (w * 16 + lr) * 65 + q * 8 + 2 * lc]         = g[q][0];
                sm[SG_O + (w * 16 + lr) * 65 + q * 8 + 2 * lc + 1]     = g[q][1];
                sm[SG_O + (w * 16 + 8 + lr) * 65 + q * 8 + 2 * lc]     = g[q][2];
                sm[SG_O + (w * 16 + 8 + lr) * 65 + q * 8 + 2 * lc + 1] = g[q][3];
            }
        }
        __syncthreads();

        // ---- y_diag (3-way over m) + projected state partials ----
        if (tid < 192) {
            int l = tid & 63, hh = tid >> 6;
            float cuml = sm[SCUM_O + l];
            float acc2 = 0.f;
            for (int m = hh; m <= l; m += 3)
                acc2 += sm[SG_O + l * 65 + m] * sm[SWS_O + m]
                      * __expf(clip20(cuml - sm[SCUM_O + m]));
            sm[SYD_O + hh * 64 + l] = acc2;
        } else {
            int j = tid - 192, i = j & 15, part = j >> 4;
            float acc2 = 0.f;
#pragma unroll
            for (int q = 0; q < 16; ++q) {
                int l = part * 16 + q;
                acc2 = fmaf(sm[SB_O + l * 17 + i], sm[SWS_O + l] * sm[SDEC_O + l], acc2);
            }
            sm[SSR_O + j] = acc2;
        }
        __syncthreads();

        // ---- finalize chunk ----
        if (tid < 64) {
            int t = chunk * 64 + tid;
            float dx   = sm[SDX_O + tid];
            float base = sm[SYD_O + tid] + sm[SYD_O + 64 + tid] + sm[SYD_O + 128 + tid] + rb
                       + (dx >= 0.f ? dx : 0.01f * dx);
            g_base[t * 64 + n] = base;
            g_cum[t * 64 + n]  = sm[SCUM_O + tid];
        } else if (tid < 80) {
            int i = tid - 64;
            g_sr[(n * 64 + chunk) * 16 + i] = sm[SSR_O + i] + sm[SSR_O + 16 + i]
                                            + sm[SSR_O + 32 + i] + sm[SSR_O + 48 + i];
        }
    }
}

// ---------- K2: inter-chunk recurrence ----------
__global__ void k_scan() {
    __shared__ float ssr[64 * 16];
    __shared__ float sdc[64];
    const int n = blockIdx.x, tid = threadIdx.x;
    for (int i = tid; i < 1024; i += 64) ssr[i] = g_sr[n * 1024 + i];
    sdc[tid] = g_dch[n * 64 + tid];
    __syncthreads();
    if (tid < 16) {
        float h = 0.f;
        for (int c = 0; c < 64; ++c) {
            g_hr[(c * 64 + n) * 16 + tid] = h;
            h = sdc[c] * h + ssr[c * 16 + tid];
        }
    }
}

// ---------- K3: out = base + exp(cum) * (C . hr) ----------
__global__ __launch_bounds__(256) void k_final(float* __restrict__ out) {
    __shared__ float hr[1024];
    const int chunk = blockIdx.x;
    const int lg = blockIdx.y;            // 0..15
    const int tid = threadIdx.x;
    for (int i = tid; i < 1024; i += 256) hr[i] = g_hr[chunk * 1024 + i];
    __syncthreads();
    const int nn = tid & 63;
    const int l = lg * 4 + (tid >> 6);
    const int t = chunk * 64 + l;
    const float4* Cp = (const float4*)(g_C + (t * 64 + nn) * 16);
    float4 c0 = Cp[0], c1 = Cp[1], c2 = Cp[2], c3 = Cp[3];
    const float* h = hr + nn * 16;
    float acc = c0.x*h[0] + c0.y*h[1] + c0.z*h[2] + c0.w*h[3]
              + c1.x*h[4] + c1.y*h[5] + c1.z*h[6] + c1.w*h[7]
              + c2.x*h[8] + c2.y*h[9] + c2.z*h[10] + c2.w*h[11]
              + c3.x*h[12] + c3.y*h[13] + c3.z*h[14] + c3.w*h[15];
    out[t * 64 + nn] = g_base[t * 64 + nn] + __expf(g_cum[t * 64 + nn]) * acc;
}

// ---------- launch ----------
extern "C" void kernel_launch(void* const* d_in, const int* in_sizes, int n_in,
                              void* d_out, int out_size) {
    const float* x        = (const float*)d_in[0];
    const float* conv_w   = (const float*)d_in[1];
    const float* conv_b   = (const float*)d_in[2];
    const float* pass_w   = (const float*)d_in[3];
    const float* pass_b   = (const float*)d_in[4];
    const float* red_w    = (const float*)d_in[5];
    const float* red_b    = (const float*)d_in[6];
    const float* dt_param = (const float*)d_in[7];
    float* out = (float*)d_out;

    const int smem_bytes = SMEMF * (int)sizeof(float);
    cudaFuncSetAttribute(k_main, cudaFuncAttributeMaxDynamicSharedMemorySize, smem_bytes);

    k_wt<<<(320 * 104 + 255) / 256, 256>>>(conv_w);
    k_main<<<dim3(NCHUNK / TPB, NSEQ), 256, smem_bytes>>>(x, conv_b, pass_w, pass_b,
                                                          red_w, red_b, dt_param);
    k_scan<<<NSEQ, 64>>>();
    k_final<<<dim3(NCHUNK, 16), 256>>>(out);
}